// round 5
// baseline (speedup 1.0000x reference)
#include <cuda_runtime.h>
#include <math.h>
#include <stdint.h>

#define BATCH 4096
#define DX 128
#define TT 81
#define DH 1024
#define KIN 257
#define KINP 288
#define DD 128
#define NSTEP 64
#define NDLY 16
#define DTC 0.02f
#define EPSB 1e-5f

#define KT_IN 36      /* 288/8  k-tiles, input layer  */
#define KT_H  128     /* 1024/8 k-tiles, hidden/out   */

/* B' (weights, split+tiled): [ntile][ktile][lane(32)][b0h,b1h,b0l,b1l] */
#define BIN_OFF  0
#define BIN_SZ   (128 * KT_IN * 128)
#define BH_OFF   (BIN_OFF + BIN_SZ)
#define BH_SZ    (128 * KT_H * 128)
#define BOUT_OFF (BH_OFF + 3 * BH_SZ)
#define BOUT_SZ  (16 * KT_H * 128)
#define BSP_TOTAL (BOUT_OFF + BOUT_SZ)

// ---------------- device scratch ----------------
__device__ float g_Bsp[BSP_TOTAL];           // weights split hi/lo, tile layout
__device__ float g_t0[BATCH * DH];           // raw activations, A-tile layout (ping)
__device__ float g_t1[BATCH * DH];           // raw activations, A-tile layout (pong)
__device__ float g_zt[BATCH * DD];           // z_t (row-major)
__device__ float g_cs[4][DH];                // per-layer column-sum accumulators
__device__ float g_cq[4][DH];                // per-layer column-sumsq accumulators
__device__ float g_xsum[DX * TT];            // x column stats (all t), written once
__device__ float g_xsq[DX * TT];

// ---------------- helpers ----------------
__device__ __forceinline__ uint32_t smem_u32(const void* p) {
    uint32_t a;
    asm("{ .reg .u64 t; cvta.to.shared.u64 t, %1; cvt.u32.u64 %0, t; }" : "=r"(a) : "l"(p));
    return a;
}
__device__ __forceinline__ uint32_t tf32_rna(float x) {
    uint32_t u; asm("cvt.rna.tf32.f32 %0, %1;" : "=r"(u) : "f"(x)); return u;
}
__device__ __forceinline__ void split_tf32(float x, float& h, float& l) {
    uint32_t hu = tf32_rna(x);
    float hf = __uint_as_float(hu);
    h = hf;
    l = __uint_as_float(tf32_rna(x - hf));
}
__device__ __forceinline__ void lds128(uint32_t* r, uint32_t a) {
    asm volatile("ld.shared.v4.b32 {%0,%1,%2,%3}, [%4];"
                 : "=r"(r[0]), "=r"(r[1]), "=r"(r[2]), "=r"(r[3]) : "r"(a));
}
__device__ __forceinline__ void sts128f(uint32_t a, float x, float y, float z, float w) {
    asm volatile("st.shared.v4.f32 [%0], {%1,%2,%3,%4};" :: "r"(a), "f"(x), "f"(y), "f"(z), "f"(w) : "memory");
}
__device__ __forceinline__ void cpasync16(uint32_t s, const void* g) {
    asm volatile("cp.async.cg.shared.global [%0], [%1], 16;" :: "r"(s), "l"(g));
}
#define CP_COMMIT() asm volatile("cp.async.commit_group;" ::: "memory")
#define CP_WAIT1()  asm volatile("cp.async.wait_group 1;" ::: "memory")
#define CP_WAIT0()  asm volatile("cp.async.wait_group 0;" ::: "memory")

__device__ __forceinline__ void mma8(float* d, const uint32_t* a, uint32_t b0, uint32_t b1) {
    asm volatile(
        "mma.sync.aligned.m16n8k8.row.col.f32.tf32.tf32.f32 "
        "{%0,%1,%2,%3}, {%4,%5,%6,%7}, {%8,%9}, {%0,%1,%2,%3};"
        : "+f"(d[0]), "+f"(d[1]), "+f"(d[2]), "+f"(d[3])
        : "r"(a[0]), "r"(a[1]), "r"(a[2]), "r"(a[3]), "r"(b0), "r"(b1));
}

// ---------------- setup: init y/z + zero stat accs + x column stats ----------------
__global__ void setup_kernel(float* yt, float* __restrict__ y, float* __restrict__ z,
                             const float* __restrict__ y0, const float* __restrict__ x) {
    int b = blockIdx.x;
    if (b < BATCH) {
        float v = y0[0];
        for (int q = threadIdx.x; q < DD * (NDLY + 1); q += blockDim.x) {
            int d = q / (NDLY + 1), t = q % (NDLY + 1);
            z[(size_t)b * DD * TT + d * TT + t] = 0.f;
        }
        if (threadIdx.x < NDLY + 1) y[b * TT + threadIdx.x] = v;
        if (threadIdx.x == 0) yt[b] = v;
    } else if (b == BATCH) {
        for (int i = threadIdx.x; i < 4 * DH; i += 256) {
            ((float*)g_cs)[i] = 0.f;
            ((float*)g_cq)[i] = 0.f;
        }
    } else {
        int p = b - BATCH - 1;         // 0 .. 128*81-1
        int d = p / TT, j = p % TT;
        float s = 0.f, q = 0.f;
        const float* base = x + (size_t)d * TT + j;
        for (int r = 0; r < 16; r++) {
            float v = base[(size_t)(threadIdx.x + r * 256) * DX * TT];
            s += v; q += v * v;
        }
#pragma unroll
        for (int off = 16; off; off >>= 1) {
            s += __shfl_down_sync(0xffffffffu, s, off);
            q += __shfl_down_sync(0xffffffffu, q, off);
        }
        __shared__ float rs[8], rq[8];
        int w = threadIdx.x >> 5;
        if ((threadIdx.x & 31) == 0) { rs[w] = s; rq[w] = q; }
        __syncthreads();
        if (threadIdx.x == 0) {
            float a = 0.f, c = 0.f;
#pragma unroll
            for (int u = 0; u < 8; u++) { a += rs[u]; c += rq[u]; }
            g_xsum[d * TT + j] = a;
            g_xsq[d * TT + j] = c;
        }
    }
}

// split all weights into tile-layout hi/lo planes (once per launch)
__global__ void split_w_kernel(const float* __restrict__ W_in, const float* __restrict__ Ws_h,
                               const float* __restrict__ W_out) {
    size_t i = (size_t)blockIdx.x * 256 + threadIdx.x;
    const size_t N_IN = (size_t)KINP * DH;
    const size_t N_H  = (size_t)DH * DH;
    const size_t N_O  = (size_t)DH * DD;
    if (i >= N_IN + 3 * N_H + N_O) return;
    int k, n, Kt; size_t base; float v;
    if (i < N_IN) {
        k = (int)(i / DH); n = (int)(i % DH);
        v = (k < KIN) ? W_in[(size_t)k * DH + n] : 0.f;
        Kt = KT_IN; base = BIN_OFF;
    } else if (i < N_IN + 3 * N_H) {
        size_t j = i - N_IN;
        int l = (int)(j / N_H); size_t r = j % N_H;
        k = (int)(r / DH); n = (int)(r % DH);
        v = Ws_h[(size_t)l * N_H + (size_t)k * DH + n];
        Kt = KT_H; base = BH_OFF + (size_t)l * BH_SZ;
    } else {
        size_t j = i - N_IN - 3 * N_H;
        k = (int)(j / DD); n = (int)(j % DD);
        v = W_out[(size_t)k * DD + n];
        Kt = KT_H; base = BOUT_OFF;
    }
    float h, l2;
    split_tf32(v, h, l2);
    int nt = n >> 3, kt = k >> 3;
    int lane = (n & 7) * 4 + (k & 3);
    int w = (k & 7) >> 2;
    size_t off = base + ((size_t)(nt * Kt + kt) * 32 + lane) * 4;
    g_Bsp[off + w]     = h;
    g_Bsp[off + w + 2] = l2;
}

// ---------------- per-step: gather + input-BN fold -> raw A-tile layout (Kt=36) ----------------
__global__ void gather_kernel(const float* __restrict__ x,
                              const float* __restrict__ gg,
                              const float* __restrict__ bb, int i) {
    int idx = blockIdx.x * 256 + threadIdx.x;
    int lane = idx & 31;
    int t2 = idx >> 5;
    int kt = t2 % KT_IN, mt = t2 / KT_IN;
    int m0 = mt * 16 + (lane >> 2);
    int k0 = kt * 8 + (lane & 3);
    int it = i + NDLY;

    float av[2], cv[2];
#pragma unroll
    for (int h = 0; h < 2; h++) {
        int k = k0 + h * 4;
        float a = 0.f, c = 0.f;
        if (k < 2 * DX) {
            int d  = (k < DX) ? k  : k - DX;
            int tt = (k < DX) ? it : i;
            float s = g_xsum[d * TT + tt], q = g_xsq[d * TT + tt];
            float m = s * (1.f / BATCH);
            float v = q * (1.f / BATCH) - m * m;
            if (v < 0.f) v = 0.f;
            a = gg[k] * rsqrtf(v + EPSB);
            c = bb[k] - m * a;
        } else if (k == 2 * DX) {
            c = bb[k];      // constant-t column: var==0 analytically
        }
        av[h] = a; cv[h] = c;
    }

    float4 f;
    {
        float r0 = 0.f, r1 = 0.f, r2 = 0.f, r3 = 0.f;
        if (k0 < DX) {
            r0 = x[(size_t)m0 * DX * TT + k0 * TT + it];
            r1 = x[(size_t)(m0 + 8) * DX * TT + k0 * TT + it];
        } else if (k0 < 2 * DX) {
            r0 = x[(size_t)m0 * DX * TT + (k0 - DX) * TT + i];
            r1 = x[(size_t)(m0 + 8) * DX * TT + (k0 - DX) * TT + i];
        }
        int k4 = k0 + 4;
        if (k4 < DX) {
            r2 = x[(size_t)m0 * DX * TT + k4 * TT + it];
            r3 = x[(size_t)(m0 + 8) * DX * TT + k4 * TT + it];
        } else if (k4 < 2 * DX) {
            r2 = x[(size_t)m0 * DX * TT + (k4 - DX) * TT + i];
            r3 = x[(size_t)(m0 + 8) * DX * TT + (k4 - DX) * TT + i];
        }
        f.x = fmaf(r0, av[0], cv[0]);
        f.y = fmaf(r1, av[0], cv[0]);
        f.z = fmaf(r2, av[1], cv[1]);
        f.w = fmaf(r3, av[1], cv[1]);
    }
    *(float4*)(g_t0 + ((size_t)(mt * KT_IN + kt) * 32 + lane) * 4) = f;
}

// ---------------- 3xTF32 mma.sync GEMM, fused BN-fold/split producer ----------------
// A: raw fp32 tile layout [mtile][ktile][lane][m0k0,m8k0,m0k4,m8k4]
// smem stage (64KB): [Ahi 16K][Alo 16K][B 32K]; double buffered.
__global__ __launch_bounds__(256, 1)
void gemm_mma_kernel(const float* __restrict__ Ap, int Kt, int chunks,
                     const float* __restrict__ Bp,
                     const float* __restrict__ csP, const float* __restrict__ cqP,
                     const float* __restrict__ gg, const float* __restrict__ bb,
                     const float* __restrict__ bias,
                     float* __restrict__ out, int ldo, int tile_out, int do_tanh,
                     float* __restrict__ csum, float* __restrict__ csq) {
    extern __shared__ float smf[];
    __shared__ float sa[DH], sc[DH];
    __shared__ float scol[128], ssq[128];
    const uint32_t sbase = smem_u32(smf);
    const int tid = threadIdx.x;
    const int mt0 = blockIdx.y * 8;
    const int nt0 = blockIdx.x * 16;
    const int w = tid >> 5, lane = tid & 31;
    const int wm = w & 3, wn2 = w >> 2;
    const bool fold = (csP != nullptr);

    if (fold) {
        for (int k = tid; k < Kt * 8; k += 256) {
            float m = csP[k] * (1.f / BATCH);
            float v = cqP[k] * (1.f / BATCH) - m * m;
            if (v < 0.f) v = 0.f;
            float a = gg[k] * rsqrtf(v + EPSB);
            sa[k] = a;
            sc[k] = bb[k] - m * a;
        }
    }
    __syncthreads();

    const float4* Ap4 = (const float4*)Ap;

    // ---- producer lambdas (inlined) ----
    float4 rbuf[4];
#define LOAD_A(kc_)                                                              \
    {                                                                            \
        _Pragma("unroll")                                                        \
        for (int i_ = 0; i_ < 4; i_++) {                                         \
            int idx_ = i_ * 256 + tid;                                           \
            int mt_ = idx_ >> 7, kt_ = (idx_ >> 5) & 3, ln_ = idx_ & 31;         \
            rbuf[i_] = __ldg(Ap4 + ((size_t)(mt0 + mt_) * Kt + (kc_) * 4 + kt_) * 32 + ln_); \
        }                                                                        \
    }
#define STORE_A(kc_, st_)                                                        \
    {                                                                            \
        uint32_t base_ = sbase + (st_) * 65536;                                  \
        _Pragma("unroll")                                                        \
        for (int i_ = 0; i_ < 4; i_++) {                                         \
            int idx_ = i_ * 256 + tid;                                           \
            int mt_ = idx_ >> 7, kt_ = (idx_ >> 5) & 3, ln_ = idx_ & 31;         \
            float4 v_ = rbuf[i_];                                                \
            if (fold) {                                                          \
                int k0_ = ((kc_) * 4 + kt_) * 8 + (ln_ & 3);                     \
                float a0_ = sa[k0_], c0_ = sc[k0_];                              \
                float a4_ = sa[k0_ + 4], c4_ = sc[k0_ + 4];                      \
                v_.x = fmaf(v_.x, a0_, c0_); v_.y = fmaf(v_.y, a0_, c0_);        \
                v_.z = fmaf(v_.z, a4_, c4_); v_.w = fmaf(v_.w, a4_, c4_);        \
            }                                                                    \
            float hx_, lx_, hy_, ly_, hz_, lz_, hw_, lw_;                        \
            split_tf32(v_.x, hx_, lx_); split_tf32(v_.y, hy_, ly_);              \
            split_tf32(v_.z, hz_, lz_); split_tf32(v_.w, hw_, lw_);              \
            uint32_t off_ = (uint32_t)(((mt_ * 4 + kt_) * 32 + ln_) * 16);       \
            sts128f(base_ + off_, hx_, hy_, hz_, hw_);                           \
            sts128f(base_ + 16384 + off_, lx_, ly_, lz_, lw_);                   \
        }                                                                        \
    }
#define LOAD_B(kc_, st_)                                                         \
    {                                                                            \
        uint32_t bb_ = sbase + (st_) * 65536 + 32768;                            \
        const int bnt_ = tid >> 7, brem_ = tid & 127;                            \
        const int bkt_ = brem_ >> 5, bcid_ = brem_ & 31;                         \
        _Pragma("unroll")                                                        \
        for (int i_ = 0; i_ < 8; i_++) {                                         \
            int nt_ = i_ * 2 + bnt_;                                             \
            const float* src_ = Bp + ((size_t)(nt0 + nt_) * Kt + (kc_) * 4 + bkt_) * 128 + bcid_ * 4; \
            cpasync16(bb_ + (uint32_t)(((nt_ * 4 + bkt_) * 128 + bcid_ * 4) * 4), src_); \
        }                                                                        \
    }

    float acc[2][8][4];
#pragma unroll
    for (int mi = 0; mi < 2; mi++)
#pragma unroll
        for (int ni = 0; ni < 8; ni++)
#pragma unroll
            for (int r = 0; r < 4; r++) acc[mi][ni][r] = 0.f;

    // prologue: build stage 0, prefetch A(1) regs
    LOAD_A(0);
    STORE_A(0, 0);
    LOAD_B(0, 0);
    CP_COMMIT();
    if (chunks > 1) LOAD_A(1);

    for (int kc = 0; kc < chunks; kc++) {
        const int st = kc & 1;
        if (kc + 1 < chunks) {
            LOAD_B(kc + 1, st ^ 1);
            CP_COMMIT();
            STORE_A(kc + 1, st ^ 1);
            CP_WAIT1();
        } else {
            CP_WAIT0();
        }
        __syncthreads();

        if (kc + 2 < chunks) LOAD_A(kc + 2);

        const uint32_t abase = sbase + st * 65536;
        const uint32_t bbase = abase + 32768;
#pragma unroll
        for (int kk = 0; kk < 4; kk++) {
            uint32_t ah[2][4], al[2][4], bh[8][2], bl[8][2];
#pragma unroll
            for (int mi = 0; mi < 2; mi++) {
                int mt = wm * 2 + mi;
                uint32_t ad = abase + (uint32_t)((((mt * 4 + kk) * 32 + lane) * 4) * 4);
                lds128(ah[mi], ad);
                lds128(al[mi], ad + 16384);
            }
#pragma unroll
            for (int ni = 0; ni < 8; ni++) {
                int nt = wn2 * 8 + ni;
                uint32_t bf[4];
                lds128(bf, bbase + (uint32_t)((((nt * 4 + kk) * 32 + lane) * 4) * 4));
                bh[ni][0] = bf[0]; bh[ni][1] = bf[1];
                bl[ni][0] = bf[2]; bl[ni][1] = bf[3];
            }
#pragma unroll
            for (int ni = 0; ni < 8; ni++)
#pragma unroll
                for (int mi = 0; mi < 2; mi++)
                    mma8(acc[mi][ni], ah[mi], bh[ni][0], bh[ni][1]);
#pragma unroll
            for (int ni = 0; ni < 8; ni++)
#pragma unroll
                for (int mi = 0; mi < 2; mi++)
                    mma8(acc[mi][ni], ah[mi], bl[ni][0], bl[ni][1]);
#pragma unroll
            for (int ni = 0; ni < 8; ni++)
#pragma unroll
                for (int mi = 0; mi < 2; mi++)
                    mma8(acc[mi][ni], al[mi], bh[ni][0], bh[ni][1]);
        }
        __syncthreads();
    }

    // ---- epilogue ----
    const int r = lane >> 2, q = lane & 3;
    float colacc[8][4];
#pragma unroll
    for (int ni = 0; ni < 8; ni++)
#pragma unroll
        for (int u = 0; u < 4; u++) colacc[ni][u] = 0.f;

#pragma unroll
    for (int mi = 0; mi < 2; mi++) {
        int m = mt0 * 16 + wm * 32 + mi * 16 + r;
#pragma unroll
        for (int ni = 0; ni < 8; ni++) {
            int n = nt0 * 8 + wn2 * 64 + ni * 8 + 2 * q;
            float b0 = __ldg(bias + n), b1 = __ldg(bias + n + 1);
            float v0 = acc[mi][ni][0] + b0;
            float v1 = acc[mi][ni][1] + b1;
            float v2 = acc[mi][ni][2] + b0;
            float v3 = acc[mi][ni][3] + b1;
            if (do_tanh) { v0 = tanhf(v0); v1 = tanhf(v1); v2 = tanhf(v2); v3 = tanhf(v3); }
            colacc[ni][0] += v0 + v2;
            colacc[ni][1] += v1 + v3;
            colacc[ni][2] += v0 * v0 + v2 * v2;
            colacc[ni][3] += v1 * v1 + v3 * v3;
            if (tile_out) {
                // next-layer A-tile layout (ldt = 128 k-tiles)
                int base = ((((m >> 4) * KT_H + (n >> 3)) * 32 + (m & 7) * 4 + (n & 3)) << 2)
                         + 2 * ((n >> 2) & 1);
                *(float2*)(out + base)     = make_float2(v0, v2);
                *(float2*)(out + base + 4) = make_float2(v1, v3);
            } else {
                *(float2*)(out + (size_t)m * ldo + n) = make_float2(v0, v1);
                *(float2*)(out + (size_t)(m + 8) * ldo + n) = make_float2(v2, v3);
            }
        }
    }

    if (csum != nullptr) {
        if (tid < 128) { scol[tid] = 0.f; ssq[tid] = 0.f; }
        __syncthreads();
#pragma unroll
        for (int ni = 0; ni < 8; ni++) {
            float a0 = colacc[ni][0], a1 = colacc[ni][1];
            float q0 = colacc[ni][2], q1 = colacc[ni][3];
#pragma unroll
            for (int off = 4; off < 32; off <<= 1) {
                a0 += __shfl_xor_sync(0xffffffffu, a0, off);
                a1 += __shfl_xor_sync(0xffffffffu, a1, off);
                q0 += __shfl_xor_sync(0xffffffffu, q0, off);
                q1 += __shfl_xor_sync(0xffffffffu, q1, off);
            }
            if (r == 0) {
                int cn = wn2 * 64 + ni * 8 + 2 * q;
                atomicAdd(&scol[cn], a0);
                atomicAdd(&scol[cn + 1], a1);
                atomicAdd(&ssq[cn], q0);
                atomicAdd(&ssq[cn + 1], q1);
            }
        }
        __syncthreads();
        if (tid < 128) {
            int col = blockIdx.x * 128 + tid;
            atomicAdd(csum + col, scol[tid]);
            atomicAdd(csq + col, ssq[tid]);
        }
    }
#undef LOAD_A
#undef STORE_A
#undef LOAD_B
}

// ---------------- per-step state update (+ zero next-step stat buffers) ----------------
__global__ void update_kernel(const float* __restrict__ x, const float* __restrict__ dW,
                              float* yt, float* __restrict__ y, float* __restrict__ z, int i) {
    int b = blockIdx.x, d = threadIdx.x;   // 128 threads
    if (b < 32) {
        int t = b * 128 + d;
        ((float*)g_cs)[t] = 0.f;
        ((float*)g_cq)[t] = 0.f;
    }
    int it = i + NDLY;
    float zt = g_zt[b * DD + d];
    float zd = z[(size_t)b * DD * TT + d * TT + i];
    float xv = x[(size_t)b * DX * TT + d * TT + it];
    float dw = dW[(size_t)b * DD * NSTEP + d * NSTEP + i];
    z[(size_t)b * DD * TT + d * TT + it + 1] = zt;

    float p1 = zt * zd;
    float p2 = zt * dw;
    float p3 = xv;
#pragma unroll
    for (int off = 16; off; off >>= 1) {
        p1 += __shfl_down_sync(0xffffffffu, p1, off);
        p2 += __shfl_down_sync(0xffffffffu, p2, off);
        p3 += __shfl_down_sync(0xffffffffu, p3, off);
    }
    __shared__ float red[3][4];
    int w = d >> 5, lane = d & 31;
    if (lane == 0) { red[0][w] = p1; red[1][w] = p2; red[2][w] = p3; }
    __syncthreads();
    if (d == 0) {
        float s1 = red[0][0] + red[0][1] + red[0][2] + red[0][3];
        float s2 = red[1][0] + red[1][1] + red[1][2] + red[1][3];
        float s3 = red[2][0] + red[2][1] + red[2][2] + red[2][3];
        float ytp = yt[b];
        float yd  = y[b * TT + i];
        float drv = -ytp + 0.1f * yd + s1 + 0.01f * s3;
        float yn  = ytp - drv * DTC + s2;
        yt[b] = yn;
        y[b * TT + it + 1] = yn;
    }
}

// ---------------- host launch ----------------
static float* sym_addr(const void* sym) {
    void* p = nullptr;
    cudaGetSymbolAddress(&p, sym);
    return (float*)p;
}

#define GEMM_SMEM 131072

extern "C" void kernel_launch(void* const* d_in, const int* in_sizes, int n_in,
                              void* d_out, int out_size) {
    const float* x        = (const float*)d_in[0];
    const float* dW       = (const float*)d_in[1];
    const float* y0       = (const float*)d_in[2];
    const float* bn_in_g  = (const float*)d_in[3];
    const float* bn_in_b  = (const float*)d_in[4];
    const float* W_in     = (const float*)d_in[5];
    const float* b_in     = (const float*)d_in[6];
    const float* Ws_h     = (const float*)d_in[7];
    const float* bs_h     = (const float*)d_in[8];
    const float* bns_g    = (const float*)d_in[9];
    const float* bns_b    = (const float*)d_in[10];
    const float* bn_out_g = (const float*)d_in[11];
    const float* bn_out_b = (const float*)d_in[12];
    const float* W_out    = (const float*)d_in[13];
    const float* b_out    = (const float*)d_in[14];

    float* yt = (float*)d_out;
    float* y  = yt + BATCH;
    float* z  = y + (size_t)BATCH * TT;

    float* t0  = sym_addr(g_t0);
    float* t1  = sym_addr(g_t1);
    float* Bsp = sym_addr(g_Bsp);
    float* zt  = sym_addr(g_zt);
    float* cs  = sym_addr(g_cs);
    float* cq  = sym_addr(g_cq);

    cudaFuncSetAttribute(gemm_mma_kernel, cudaFuncAttributeMaxDynamicSharedMemorySize, GEMM_SMEM);

    setup_kernel<<<BATCH + 1 + DX * TT, 256>>>(yt, y, z, y0, x);
    split_w_kernel<<<13952, 256>>>(W_in, Ws_h, W_out);

    dim3 gridH(8, 32);   // N=1024
    dim3 gridO(1, 32);   // N=128

    for (int i = 0; i < NSTEP; ++i) {
        gather_kernel<<<(256 * KT_IN * 32) / 256, 256>>>(x, bn_in_g, bn_in_b, i);

        // input layer (pre-folded by gather): t0 -> t1 (tile), stats -> cs[0]
        gemm_mma_kernel<<<gridH, 256, GEMM_SMEM>>>(t0, KT_IN, KT_IN / 4, Bsp + BIN_OFF,
                                                   nullptr, nullptr, nullptr, nullptr,
                                                   b_in, t1, 0, 1, 1,
                                                   cs + 0 * DH, cq + 0 * DH);
        // hidden 1: fold with cs[0]/bns[0]: t1 -> t0, stats -> cs[1]
        gemm_mma_kernel<<<gridH, 256, GEMM_SMEM>>>(t1, KT_H, KT_H / 4, Bsp + BH_OFF,
                                                   cs + 0 * DH, cq + 0 * DH,
                                                   bns_g + 0 * DH, bns_b + 0 * DH,
                                                   bs_h + 0 * DH, t0, 0, 1, 1,
                                                   cs + 1 * DH, cq + 1 * DH);
        // hidden 2
        gemm_mma_kernel<<<gridH, 256, GEMM_SMEM>>>(t0, KT_H, KT_H / 4, Bsp + BH_OFF + BH_SZ,
                                                   cs + 1 * DH, cq + 1 * DH,
                                                   bns_g + 1 * DH, bns_b + 1 * DH,
                                                   bs_h + 1 * DH, t1, 0, 1, 1,
                                                   cs + 2 * DH, cq + 2 * DH);
        // hidden 3
        gemm_mma_kernel<<<gridH, 256, GEMM_SMEM>>>(t1, KT_H, KT_H / 4, Bsp + BH_OFF + 2 * BH_SZ,
                                                   cs + 2 * DH, cq + 2 * DH,
                                                   bns_g + 2 * DH, bns_b + 2 * DH,
                                                   bs_h + 2 * DH, t0, 0, 1, 1,
                                                   cs + 3 * DH, cq + 3 * DH);
        // output layer: fold with cs[3]/bn_out, row-major to zt, no tanh, no stats
        gemm_mma_kernel<<<gridO, 256, GEMM_SMEM>>>(t0, KT_H, KT_H / 4, Bsp + BOUT_OFF,
                                                   cs + 3 * DH, cq + 3 * DH,
                                                   bn_out_g, bn_out_b,
                                                   b_out, zt, DD, 0, 0,
                                                   nullptr, nullptr);

        update_kernel<<<BATCH, DD>>>(x, dW, yt, y, z, i);
    }
}